// round 1
// baseline (speedup 1.0000x reference)
#include <cuda_runtime.h>

#define THREADS 256
#define L 2500
#define HALF 1251          // bins 0..1250
#define PATCHES 50

__device__ __forceinline__ float2 cmul(float2 a, float2 b) {
    return make_float2(a.x * b.x - a.y * b.y, a.x * b.y + a.y * b.x);
}

// radix-5 constants (w = e^{-2pi i/5})
#define CR1 ( 0.30901699437494742f)
#define CR2 (-0.80901699437494742f)
#define SI1 ( 0.95105651629515357f)
#define SI2 ( 0.58778525229247314f)

// One Stockham DIF radix-5 stage: sub-length NN, stride SS. Natural-order autosort.
// For each (p in [0,NN/5), q in [0,SS)):
//   c_v = DFT5(a_u = X[q + SS*(p + u*NN/5)]);  Y[q + SS*(5p+v)] = c_v * e^{-2pi i p v / NN}
template <int NN, int SS>
__device__ __forceinline__ void stage5(const float2* __restrict__ X, float2* __restrict__ Y, int tid) {
    constexpr int M = NN / 5;
    constexpr int WORK = M * SS;
    for (int w = tid; w < WORK; w += THREADS) {
        const int q = w % SS;
        const int p = w / SS;
        float2 a0 = X[q + SS * p];
        float2 a1 = X[q + SS * (p + M)];
        float2 a2 = X[q + SS * (p + 2 * M)];
        float2 a3 = X[q + SS * (p + 3 * M)];
        float2 a4 = X[q + SS * (p + 4 * M)];
        float2 t1 = make_float2(a1.x + a4.x, a1.y + a4.y);
        float2 t2 = make_float2(a2.x + a3.x, a2.y + a3.y);
        float2 t3 = make_float2(a1.x - a4.x, a1.y - a4.y);
        float2 t4 = make_float2(a2.x - a3.x, a2.y - a3.y);
        float2 c0 = make_float2(a0.x + t1.x + t2.x, a0.y + t1.y + t2.y);
        float2 m1 = make_float2(a0.x + CR1 * t1.x + CR2 * t2.x, a0.y + CR1 * t1.y + CR2 * t2.y);
        float2 m2 = make_float2(a0.x + CR2 * t1.x + CR1 * t2.x, a0.y + CR2 * t1.y + CR1 * t2.y);
        float2 s1 = make_float2(SI1 * t3.x + SI2 * t4.x, SI1 * t3.y + SI2 * t4.y);
        float2 s2 = make_float2(SI2 * t3.x - SI1 * t4.x, SI2 * t3.y - SI1 * t4.y);
        float2 c1 = make_float2(m1.x + s1.y, m1.y - s1.x);  // m1 - i*s1
        float2 c4 = make_float2(m1.x - s1.y, m1.y + s1.x);  // m1 + i*s1
        float2 c2 = make_float2(m2.x + s2.y, m2.y - s2.x);  // m2 - i*s2
        float2 c3 = make_float2(m2.x - s2.y, m2.y + s2.x);  // m2 + i*s2
        // twiddles W^{p v}, W = e^{-2pi i/NN}
        float ang = -6.283185307179586f * (float)p / (float)NN;
        float sn, cs;
        sincosf(ang, &sn, &cs);
        float2 w1 = make_float2(cs, sn);
        float2 w2 = cmul(w1, w1);
        float2 w3 = cmul(w2, w1);
        float2 w4 = cmul(w2, w2);
        const int ob = q + SS * 5 * p;
        Y[ob]          = c0;
        Y[ob + SS]     = cmul(c1, w1);
        Y[ob + 2 * SS] = cmul(c2, w2);
        Y[ob + 3 * SS] = cmul(c3, w3);
        Y[ob + 4 * SS] = cmul(c4, w4);
    }
}

__global__ __launch_bounds__(THREADS)
void TimeSeriesWeighting_kernel(const float* __restrict__ x,
                                const float* __restrict__ wscal,
                                float* __restrict__ out) {
    __shared__ float2 bufA[L];
    __shared__ float2 bufB[L];
    __shared__ float s_v[THREADS / 32];
    __shared__ int   s_i[THREADS / 32];
    __shared__ int   top_idx[3];

    const int tid = threadIdx.x;
    const int b = blockIdx.x;
    const float* src = x + (long long)b * (12 * L);  // only head n=0 is used

    for (int i = tid; i < L; i += THREADS)
        bufA[i] = make_float2(src[i], 0.0f);
    __syncthreads();

    // 2500 = 5*5*5*5*4 mixed-radix Stockham (autosort -> natural-order spectrum)
    stage5<2500, 1>(bufA, bufB, tid);  __syncthreads();
    stage5<500, 5>(bufB, bufA, tid);   __syncthreads();
    stage5<100, 25>(bufA, bufB, tid);  __syncthreads();
    stage5<20, 125>(bufB, bufA, tid);  __syncthreads();
    // final radix-4 stage: NN=4, SS=625, p=0 (twiddle = 1)
    for (int q = tid; q < 625; q += THREADS) {
        float2 a0 = bufA[q], a1 = bufA[q + 625], a2 = bufA[q + 1250], a3 = bufA[q + 1875];
        float2 e0 = make_float2(a0.x + a2.x, a0.y + a2.y);
        float2 e1 = make_float2(a0.x - a2.x, a0.y - a2.y);
        float2 o0 = make_float2(a1.x + a3.x, a1.y + a3.y);
        float2 o1 = make_float2(a1.x - a3.x, a1.y - a3.y);
        bufB[q]        = make_float2(e0.x + o0.x, e0.y + o0.y);
        bufB[q + 625]  = make_float2(e1.x + o1.y, e1.y - o1.x);  // e1 - i*o1
        bufB[q + 1250] = make_float2(e0.x - o0.x, e0.y - o0.y);
        bufB[q + 1875] = make_float2(e1.x - o1.y, e1.y + o1.x);  // e1 + i*o1
    }
    __syncthreads();

    // power spectrum, half only (k = 0..1250); reuse bufA as float scratch
    float* pw = reinterpret_cast<float*>(bufA);
    for (int k = tid; k < HALF; k += THREADS) {
        float2 v = bufB[k];
        pw[k] = v.x * v.x + v.y * v.y;
    }
    __syncthreads();

    // top-3 half-spectrum bins (value desc, tie -> smaller index), 3 exclusion passes
    for (int r = 0; r < 3; r++) {
        const int e0 = (r > 0) ? top_idx[0] : -1;
        const int e1 = (r > 1) ? top_idx[1] : -1;
        float bv = -1.0f;
        int bi = 0x7fffffff;
        for (int k = tid; k < HALF; k += THREADS) {
            if (k == e0 || k == e1) continue;
            float v = pw[k];
            if (v > bv || (v == bv && k < bi)) { bv = v; bi = k; }
        }
        #pragma unroll
        for (int off = 16; off > 0; off >>= 1) {
            float ov = __shfl_down_sync(0xffffffffu, bv, off);
            int   oi = __shfl_down_sync(0xffffffffu, bi, off);
            if (ov > bv || (ov == bv && oi < bi)) { bv = ov; bi = oi; }
        }
        if ((tid & 31) == 0) { s_v[tid >> 5] = bv; s_i[tid >> 5] = bi; }
        __syncthreads();
        if (tid == 0) {
            float fv = s_v[0]; int fi = s_i[0];
            #pragma unroll
            for (int wv = 1; wv < THREADS / 32; wv++) {
                if (s_v[wv] > fv || (s_v[wv] == fv && s_i[wv] < fi)) { fv = s_v[wv]; fi = s_i[wv]; }
            }
            top_idx[r] = fi;
        }
        __syncthreads();
    }

    // Map full-spectrum ranks {0, 2} onto half-spectrum bins with multiplicity:
    // DC (0) and Nyquist (1250) appear once; every other bin k appears twice (k, 2500-k).
    const int h0 = top_idx[0], h1 = top_idx[1], h2 = top_idx[2];
    const bool h0_pair = (h0 != 0 && h0 != 1250);
    const bool h1_pair = (h1 != 0 && h1 != 1250);
    const int ka = h0;                                   // full rank 0
    const int kb = h0_pair ? h1 : (h1_pair ? h1 : h2);   // full rank 2

    if (tid < PATCHES) {
        const float wgt = 12.0f * wscal[0];  // N * weights
        const int start = tid * 50;
        int cnt = 0;
        if (ka != 0) {
            int p = L / ka;
            int fm = ((start + p - 1) / p) * p;
            cnt += (fm < start + 50);
        }
        if (kb != 0) {
            int p = L / kb;
            int fm = ((start + p - 1) / p) * p;
            cnt += (fm < start + 50);
        }
        out[b * PATCHES + tid] = wgt * (float)cnt;
    }
}

extern "C" void kernel_launch(void* const* d_in, const int* in_sizes, int n_in,
                              void* d_out, int out_size) {
    const float* x = (const float*)d_in[0];
    const float* w = (const float*)d_in[1];
    int xs = in_sizes[0];
    if (n_in >= 2 && in_sizes[0] < in_sizes[1]) {  // scalar weights vs big x, order-robust
        x = (const float*)d_in[1];
        w = (const float*)d_in[0];
        xs = in_sizes[1];
    }
    const int B = xs / (12 * L);  // 1024
    TimeSeriesWeighting_kernel<<<B, THREADS>>>(x, w, (float*)d_out);
}

// round 2
// speedup vs baseline: 1.4877x; 1.4877x over previous
#include <cuda_runtime.h>

#define THREADS 256
#define L 2500
#define HALF 1251          // bins 0..1250
#define PATCHES 50
#define TWN 500            // master twiddle table: W_2500^j, j=0..499

__device__ __forceinline__ float2 cmul(float2 a, float2 b) {
    return make_float2(a.x * b.x - a.y * b.y, a.x * b.y + a.y * b.x);
}

// radix-5 constants (w = e^{-2pi i/5})
#define CR1 ( 0.30901699437494742f)
#define CR2 (-0.80901699437494742f)
#define SI1 ( 0.95105651629515357f)
#define SI2 ( 0.58778525229247314f)

// Stockham DIF radix-5 stage, natural-order autosort.
// Twiddle w1 = W_2500^(p * (2500/NN)); p < NN/5 <= 500 so one 500-entry table serves all stages.
template <int NN, int SS>
__device__ __forceinline__ void stage5(const float2* __restrict__ X, float2* __restrict__ Y,
                                       const float2* __restrict__ tw, int tid) {
    constexpr int M = NN / 5;
    constexpr int STRIDE = 2500 / NN;
    constexpr int WORK = M * SS;   // always 500
    for (int w = tid; w < WORK; w += THREADS) {
        const int q = w % SS;
        const int p = w / SS;
        float2 a0 = X[q + SS * p];
        float2 a1 = X[q + SS * (p + M)];
        float2 a2 = X[q + SS * (p + 2 * M)];
        float2 a3 = X[q + SS * (p + 3 * M)];
        float2 a4 = X[q + SS * (p + 4 * M)];
        float2 t1 = make_float2(a1.x + a4.x, a1.y + a4.y);
        float2 t2 = make_float2(a2.x + a3.x, a2.y + a3.y);
        float2 t3 = make_float2(a1.x - a4.x, a1.y - a4.y);
        float2 t4 = make_float2(a2.x - a3.x, a2.y - a3.y);
        float2 c0 = make_float2(a0.x + t1.x + t2.x, a0.y + t1.y + t2.y);
        float2 m1 = make_float2(a0.x + CR1 * t1.x + CR2 * t2.x, a0.y + CR1 * t1.y + CR2 * t2.y);
        float2 m2 = make_float2(a0.x + CR2 * t1.x + CR1 * t2.x, a0.y + CR2 * t1.y + CR1 * t2.y);
        float2 s1 = make_float2(SI1 * t3.x + SI2 * t4.x, SI1 * t3.y + SI2 * t4.y);
        float2 s2 = make_float2(SI2 * t3.x - SI1 * t4.x, SI2 * t3.y - SI1 * t4.y);
        float2 c1 = make_float2(m1.x + s1.y, m1.y - s1.x);
        float2 c4 = make_float2(m1.x - s1.y, m1.y + s1.x);
        float2 c2 = make_float2(m2.x + s2.y, m2.y - s2.x);
        float2 c3 = make_float2(m2.x - s2.y, m2.y + s2.x);
        float2 w1 = tw[p * STRIDE];
        float2 w2 = cmul(w1, w1);
        float2 w3 = cmul(w2, w1);
        float2 w4 = cmul(w2, w2);
        const int ob = q + SS * 5 * p;
        Y[ob]          = c0;
        Y[ob + SS]     = cmul(c1, w1);
        Y[ob + 2 * SS] = cmul(c2, w2);
        Y[ob + 3 * SS] = cmul(c3, w3);
        Y[ob + 4 * SS] = cmul(c4, w4);
    }
}

__global__ __launch_bounds__(THREADS)
void TimeSeriesWeighting_kernel(const float* __restrict__ x,
                                const float* __restrict__ wscal,
                                float* __restrict__ out) {
    __shared__ float2 bufA[L];
    __shared__ float2 bufB[L];
    __shared__ float2 tw[TWN];
    __shared__ float s_v[THREADS / 32];
    __shared__ int   s_i[THREADS / 32];
    __shared__ int   top_idx[2][3];

    const int tid = threadIdx.x;
    const long long b0 = 2LL * blockIdx.x;

    // Pack two batches' head-0 rows into one complex signal: z = x_a + i*x_b.
    // Rows are 12*2500 = 30000 floats apart (16B-divisible) -> float4 loads.
    const float4* sa = reinterpret_cast<const float4*>(x + b0 * 30000);
    const float4* sb = reinterpret_cast<const float4*>(x + (b0 + 1) * 30000);
    for (int i = tid; i < 625; i += THREADS) {
        float4 va = sa[i], vb = sb[i];
        int j = i * 4;
        bufA[j]     = make_float2(va.x, vb.x);
        bufA[j + 1] = make_float2(va.y, vb.y);
        bufA[j + 2] = make_float2(va.z, vb.z);
        bufA[j + 3] = make_float2(va.w, vb.w);
    }
    // Master twiddle table (2 sincosf per thread, once per CTA)
    for (int j = tid; j < TWN; j += THREADS) {
        float sn, cs;
        sincosf(-6.283185307179586f * (float)j / 2500.0f, &sn, &cs);
        tw[j] = make_float2(cs, sn);
    }
    __syncthreads();

    // 2500 = 5*5*5*5*4 mixed-radix Stockham (autosort -> natural order)
    stage5<2500, 1>(bufA, bufB, tw, tid);  __syncthreads();
    stage5<500, 5>(bufB, bufA, tw, tid);   __syncthreads();
    stage5<100, 25>(bufA, bufB, tw, tid);  __syncthreads();
    stage5<20, 125>(bufB, bufA, tw, tid);  __syncthreads();
    // final radix-4 stage: NN=4, SS=625, twiddle = 1
    for (int q = tid; q < 625; q += THREADS) {
        float2 a0 = bufA[q], a1 = bufA[q + 625], a2 = bufA[q + 1250], a3 = bufA[q + 1875];
        float2 e0 = make_float2(a0.x + a2.x, a0.y + a2.y);
        float2 e1 = make_float2(a0.x - a2.x, a0.y - a2.y);
        float2 o0 = make_float2(a1.x + a3.x, a1.y + a3.y);
        float2 o1 = make_float2(a1.x - a3.x, a1.y - a3.y);
        bufB[q]        = make_float2(e0.x + o0.x, e0.y + o0.y);
        bufB[q + 625]  = make_float2(e1.x + o1.y, e1.y - o1.x);
        bufB[q + 1250] = make_float2(e0.x - o0.x, e0.y - o0.y);
        bufB[q + 1875] = make_float2(e1.x - o1.y, e1.y + o1.x);
    }
    __syncthreads();

    // Split packed spectrum into two power spectra (uniform x4 factor, argmax-invariant):
    //   pw_a[k] = |Z[k] + conj(Z[N-k])|^2 ,  pw_b[k] = |Z[k] - conj(Z[N-k])|^2
    float* pa = reinterpret_cast<float*>(bufA);   // 1251 floats
    float* pb = pa + 1280;                        // 1251 floats (fits in bufA's 5000 floats)
    for (int k = tid; k < HALF; k += THREADS) {
        float2 zk = bufB[k];
        float2 zm = bufB[k == 0 ? 0 : (L - k)];
        float sx = zk.x + zm.x, sy = zk.y - zm.y;
        float dx = zk.x - zm.x, dy = zk.y + zm.y;
        pa[k] = sx * sx + sy * sy;
        pb[k] = dx * dx + dy * dy;
    }
    __syncthreads();

    // Top-3 half-spectrum bins per batch; group 0 = threads 0..127 (batch a),
    // group 1 = threads 128..255 (batch b).
    const int g = tid >> 7;
    const int lt = tid & 127;
    const float* pw = g ? pb : pa;
    for (int r = 0; r < 3; r++) {
        const int e0 = (r > 0) ? top_idx[g][0] : -1;
        const int e1 = (r > 1) ? top_idx[g][1] : -1;
        float bv = -1.0f;
        int bi = 0x7fffffff;
        for (int k = lt; k < HALF; k += 128) {
            if (k == e0 || k == e1) continue;
            float v = pw[k];
            if (v > bv || (v == bv && k < bi)) { bv = v; bi = k; }
        }
        #pragma unroll
        for (int off = 16; off > 0; off >>= 1) {
            float ov = __shfl_down_sync(0xffffffffu, bv, off);
            int   oi = __shfl_down_sync(0xffffffffu, bi, off);
            if (ov > bv || (ov == bv && oi < bi)) { bv = ov; bi = oi; }
        }
        if ((tid & 31) == 0) { s_v[tid >> 5] = bv; s_i[tid >> 5] = bi; }
        __syncthreads();
        if (lt == 0) {
            const int base = g * 4;
            float fv = s_v[base]; int fi = s_i[base];
            #pragma unroll
            for (int wv = 1; wv < 4; wv++) {
                float v2 = s_v[base + wv]; int i2 = s_i[base + wv];
                if (v2 > fv || (v2 == fv && i2 < fi)) { fv = v2; fi = i2; }
            }
            top_idx[g][r] = fi;
        }
        __syncthreads();
    }

    // Map full-spectrum ranks {0, 2} onto half-spectrum bins with multiplicity:
    // DC (0) and Nyquist (1250) appear once; other bins appear twice (k, 2500-k).
    const int h0 = top_idx[g][0], h1 = top_idx[g][1], h2 = top_idx[g][2];
    const bool h0_pair = (h0 != 0 && h0 != 1250);
    const bool h1_pair = (h1 != 0 && h1 != 1250);
    const int ka = h0;
    const int kb = (h0_pair || h1_pair) ? h1 : h2;

    if (lt < PATCHES) {
        const float wgt = 12.0f * wscal[0];  // N * weights
        const int start = lt * 50;
        int cnt = 0;
        if (ka != 0) {
            int p = L / ka;
            int fm = ((start + p - 1) / p) * p;
            cnt += (fm < start + 50);
        }
        if (kb != 0) {
            int p = L / kb;
            int fm = ((start + p - 1) / p) * p;
            cnt += (fm < start + 50);
        }
        out[(b0 + g) * PATCHES + lt] = wgt * (float)cnt;
    }
}

extern "C" void kernel_launch(void* const* d_in, const int* in_sizes, int n_in,
                              void* d_out, int out_size) {
    const float* x = (const float*)d_in[0];
    const float* w = (const float*)d_in[1];
    int xs = in_sizes[0];
    if (n_in >= 2 && in_sizes[0] < in_sizes[1]) {  // order-robust: scalar vs big tensor
        x = (const float*)d_in[1];
        w = (const float*)d_in[0];
        xs = in_sizes[1];
    }
    const int B = xs / (12 * L);   // 1024
    TimeSeriesWeighting_kernel<<<B / 2, THREADS>>>(x, w, (float*)d_out);
}